// round 2
// baseline (speedup 1.0000x reference)
#include <cuda_runtime.h>
#include <cstdint>

// Problem constants (fixed-shape problem)
#define B_  4
#define S_  2048
#define D_  1024
#define H_  16
#define DH_ 64
#define M_  (B_ * S_)   // 8192 rows for all projections

// ---------------------------------------------------------------------------
// Scratch (device globals: allocation-free, graph-capturable)
// q,k,v in [B,H,S,Dh]; o_concat in [B,S,D]
// ---------------------------------------------------------------------------
__device__ float g_q[B_ * H_ * S_ * DH_];
__device__ float g_k[B_ * H_ * S_ * DH_];
__device__ float g_v[B_ * H_ * S_ * DH_];
__device__ float g_o[B_ * S_ * D_];

// ---------------------------------------------------------------------------
// GEMM (NT): C[M,N] = A[M,K] * W[N,K]^T + bias[N]
// MODE 0: C row-major [M,N]
// MODE 1: scatter to [B,H,S,Dh]  (row = b*S+s, col = h*64+dh)
// Tiling: 128x128 block, BK=8, 256 threads, 8x8 per-thread microtile.
// ---------------------------------------------------------------------------
template <int MODE>
__global__ __launch_bounds__(256) void gemm_nt(
    const float* __restrict__ A, const float* __restrict__ W,
    const float* __restrict__ bias, float* __restrict__ C,
    int M, int N, int K)
{
    __shared__ float As[8][128];  // transposed: As[k][m]
    __shared__ float Ws[8][128];  // transposed: Ws[k][n]

    const int tid = threadIdx.x;
    const int tx = tid & 15;       // 0..15
    const int ty = tid >> 4;       // 0..15
    const int bm = blockIdx.y * 128;
    const int bn = blockIdx.x * 128;

    // gmem load mapping: thread loads one float4 from A and one from W per BK step
    const int lr = tid >> 1;            // 0..127 (row within tile)
    const int lc = (tid & 1) * 4;       // 0 or 4 (k offset within BK)
    const float* Ap = A + (size_t)(bm + lr) * K + lc;
    const float* Wp = W + (size_t)(bn + lr) * K + lc;

    float acc[8][8];
#pragma unroll
    for (int i = 0; i < 8; i++)
#pragma unroll
        for (int j = 0; j < 8; j++) acc[i][j] = 0.0f;

    float4 av = *(const float4*)Ap;
    float4 wv = *(const float4*)Wp;

    for (int k0 = 0; k0 < K; k0 += 8) {
        // stage current tile into smem (transposed)
        As[lc + 0][lr] = av.x; As[lc + 1][lr] = av.y;
        As[lc + 2][lr] = av.z; As[lc + 3][lr] = av.w;
        Ws[lc + 0][lr] = wv.x; Ws[lc + 1][lr] = wv.y;
        Ws[lc + 2][lr] = wv.z; Ws[lc + 3][lr] = wv.w;
        __syncthreads();

        // prefetch next tile (overlap gmem latency with compute)
        if (k0 + 8 < K) {
            av = *(const float4*)(Ap + k0 + 8);
            wv = *(const float4*)(Wp + k0 + 8);
        }

#pragma unroll
        for (int k = 0; k < 8; k++) {
            float a[8], b[8];
            *(float4*)(a)     = *(const float4*)&As[k][ty * 8];
            *(float4*)(a + 4) = *(const float4*)&As[k][ty * 8 + 4];
            *(float4*)(b)     = *(const float4*)&Ws[k][tx * 8];
            *(float4*)(b + 4) = *(const float4*)&Ws[k][tx * 8 + 4];
#pragma unroll
            for (int i = 0; i < 8; i++)
#pragma unroll
                for (int j = 0; j < 8; j++)
                    acc[i][j] = fmaf(a[i], b[j], acc[i][j]);
        }
        __syncthreads();
    }

    // epilogue
#pragma unroll
    for (int i = 0; i < 8; i++) {
        const int row = bm + ty * 8 + i;
#pragma unroll
        for (int j = 0; j < 8; j++) {
            const int col = bn + tx * 8 + j;
            const float v = acc[i][j] + bias[col];
            if (MODE == 0) {
                C[(size_t)row * N + col] = v;
            } else {
                const int bb = row >> 11;          // row / S_  (S_ = 2048)
                const int ss = row & (S_ - 1);
                const int h  = col >> 6;           // col / DH_
                const int dh = col & (DH_ - 1);
                C[(((size_t)(bb * H_ + h)) * S_ + ss) * DH_ + dh] = v;
            }
        }
    }
}

// ---------------------------------------------------------------------------
// Sigmoid attention, per (b,h): O = sigmoid(Q K^T / 8) V
// Q tile: 128 rows; KV tile: 128 rows; Dh = 64.
// 256 threads. Strided thread tiles (col = tx + 16*j) => conflict-free LDS
// for the B operands. Ks padded to 65 floats/row for k-indexed column reads.
// Dynamic smem: Qs[128*64] Ks[128*65] Vs[128*64] Ps[128*128] = 164352 B.
// ---------------------------------------------------------------------------
__global__ __launch_bounds__(256) void attn_kernel(
    const float* __restrict__ Qg, const float* __restrict__ Kg,
    const float* __restrict__ Vg, float* __restrict__ Og)
{
    extern __shared__ float sm[];
    float* Qs = sm;                    // [128][64]
    float* Ks = Qs + 128 * 64;         // [128][65]
    float* Vs = Ks + 128 * 65;         // [128][64]
    float* Ps = Vs + 128 * 64;         // [128][128]

    const int tid = threadIdx.x;
    const int tx = tid & 15;
    const int ty = tid >> 4;
    const int bh = blockIdx.y;             // 0..63  (b*H + h)
    const int q0 = blockIdx.x * 128;

    const float* Qp = Qg + (size_t)bh * S_ * DH_;
    const float* Kp = Kg + (size_t)bh * S_ * DH_;
    const float* Vp = Vg + (size_t)bh * S_ * DH_;

    // load Q tile [128,64] once (2048 float4s, 8 per thread)
#pragma unroll
    for (int it = 0; it < 8; it++) {
        const int f = tid + it * 256;
        const int r = f >> 4;
        const int c = (f & 15) << 2;
        *(float4*)&Qs[r * 64 + c] =
            *(const float4*)(Qp + (size_t)(q0 + r) * DH_ + c);
    }

    float o[8][4];
#pragma unroll
    for (int i = 0; i < 8; i++)
#pragma unroll
        for (int j = 0; j < 4; j++) o[i][j] = 0.0f;

    for (int j0 = 0; j0 < S_; j0 += 128) {
        __syncthreads();  // prev iter's Ps/Vs reads complete before overwrite

        // load K (padded 65) and V (stride 64) tiles
#pragma unroll
        for (int it = 0; it < 8; it++) {
            const int f = tid + it * 256;
            const int r = f >> 4;
            const int c = (f & 15) << 2;
            const float4 kv = *(const float4*)(Kp + (size_t)(j0 + r) * DH_ + c);
            float* kd = &Ks[r * 65 + c];
            kd[0] = kv.x; kd[1] = kv.y; kd[2] = kv.z; kd[3] = kv.w;
            *(float4*)&Vs[r * 64 + c] =
                *(const float4*)(Vp + (size_t)(j0 + r) * DH_ + c);
        }
        __syncthreads();

        // Stage 1: S[128q x 128kv] = Q * K^T ; each thread: rows ty+16i, cols tx+16j
        float s[8][8];
#pragma unroll
        for (int i = 0; i < 8; i++)
#pragma unroll
            for (int j = 0; j < 8; j++) s[i][j] = 0.0f;

#pragma unroll 8
        for (int k = 0; k < DH_; k++) {
            float a[8], b[8];
#pragma unroll
            for (int i = 0; i < 8; i++) a[i] = Qs[(ty + 16 * i) * 64 + k];
#pragma unroll
            for (int j = 0; j < 8; j++) b[j] = Ks[(tx + 16 * j) * 65 + k];
#pragma unroll
            for (int i = 0; i < 8; i++)
#pragma unroll
                for (int j = 0; j < 8; j++)
                    s[i][j] = fmaf(a[i], b[j], s[i][j]);
        }

        // sigmoid(s/8) -> Ps
#pragma unroll
        for (int i = 0; i < 8; i++)
#pragma unroll
            for (int j = 0; j < 8; j++) {
                const float x = s[i][j] * 0.125f;
                Ps[(ty + 16 * i) * 128 + (tx + 16 * j)] =
                    __fdividef(1.0f, 1.0f + __expf(-x));
            }
        __syncthreads();

        // Stage 2: O[128q x 64dh] += P * V ; each thread: rows ty+16i, cols tx+16j (j<4)
#pragma unroll 8
        for (int k = 0; k < 128; k++) {
            float p[8], vv[4];
#pragma unroll
            for (int i = 0; i < 8; i++) p[i] = Ps[(ty + 16 * i) * 128 + k];
#pragma unroll
            for (int j = 0; j < 4; j++) vv[j] = Vs[k * 64 + (tx + 16 * j)];
#pragma unroll
            for (int i = 0; i < 8; i++)
#pragma unroll
                for (int j = 0; j < 4; j++)
                    o[i][j] = fmaf(p[i], vv[j], o[i][j]);
        }
    }

    // write O to concat layout [B,S,D]: o_concat[b][s][h*64+dh]
    const int bb = bh >> 4;
    const int h  = bh & (H_ - 1);
#pragma unroll
    for (int i = 0; i < 8; i++) {
        const int srow = q0 + ty + 16 * i;
#pragma unroll
        for (int j = 0; j < 4; j++) {
            const int dh = tx + 16 * j;
            Og[((size_t)bb * S_ + srow) * D_ + h * DH_ + dh] = o[i][j];
        }
    }
}

// ---------------------------------------------------------------------------
// Launcher
// ---------------------------------------------------------------------------
extern "C" void kernel_launch(void* const* d_in, const int* in_sizes, int n_in,
                              void* d_out, int out_size)
{
    const float* q  = (const float*)d_in[0];
    const float* k  = (const float*)d_in[1];
    const float* v  = (const float*)d_in[2];
    const float* Wq = (const float*)d_in[3];
    const float* bq = (const float*)d_in[4];
    const float* Wk = (const float*)d_in[5];
    const float* bk = (const float*)d_in[6];
    const float* Wv = (const float*)d_in[7];
    const float* bv = (const float*)d_in[8];
    const float* Wo = (const float*)d_in[9];
    const float* bo = (const float*)d_in[10];
    float* out = (float*)d_out;

    float *gq, *gk, *gv, *go;
    cudaGetSymbolAddress((void**)&gq, g_q);
    cudaGetSymbolAddress((void**)&gk, g_k);
    cudaGetSymbolAddress((void**)&gv, g_v);
    cudaGetSymbolAddress((void**)&go, g_o);

    const dim3 gg(D_ / 128, M_ / 128);  // (8, 64)

    gemm_nt<1><<<gg, 256>>>(q, Wq, bq, gq, M_, D_, D_);
    gemm_nt<1><<<gg, 256>>>(k, Wk, bk, gk, M_, D_, D_);
    gemm_nt<1><<<gg, 256>>>(v, Wv, bv, gv, M_, D_, D_);

    const int attn_smem = (128 * 64 + 128 * 65 + 128 * 64 + 128 * 128) * (int)sizeof(float);
    cudaFuncSetAttribute(attn_kernel, cudaFuncAttributeMaxDynamicSharedMemorySize, attn_smem);
    attn_kernel<<<dim3(S_ / 128, B_ * H_), 256, attn_smem>>>(gq, gk, gv, go);

    gemm_nt<0><<<gg, 256>>>(go, Wo, bo, out, M_, D_, D_);
}

// round 3
// speedup vs baseline: 1.0011x; 1.0011x over previous
#include <cuda_runtime.h>
#include <cstdint>

// Problem constants (fixed-shape problem)
#define B_  4
#define S_  2048
#define D_  1024
#define H_  16
#define DH_ 64
#define M_  (B_ * S_)   // 8192 rows for all projections

// ---------------------------------------------------------------------------
// Scratch (device globals: allocation-free, graph-capturable)
// q,k,v in [B,H,S,Dh]; o_concat in [B,S,D]
// ---------------------------------------------------------------------------
__device__ float g_q[B_ * H_ * S_ * DH_];
__device__ float g_k[B_ * H_ * S_ * DH_];
__device__ float g_v[B_ * H_ * S_ * DH_];
__device__ float g_o[B_ * S_ * D_];

// ---------------------------------------------------------------------------
// GEMM (NT): C[M,N] = A[M,K] * W[N,K]^T + bias[N]
// MODE 0: C row-major [M,N]
// MODE 1: scatter to [B,H,S,Dh]  (row = b*S+s, col = h*64+dh)
// Tiling: 128x128 block, BK=8, 256 threads, 8x8 per-thread microtile.
// ---------------------------------------------------------------------------
template <int MODE>
__global__ __launch_bounds__(256) void gemm_nt(
    const float* __restrict__ A, const float* __restrict__ W,
    const float* __restrict__ bias, float* __restrict__ C,
    int M, int N, int K)
{
    __shared__ float As[8][128];  // transposed: As[k][m]
    __shared__ float Ws[8][128];  // transposed: Ws[k][n]

    const int tid = threadIdx.x;
    const int tx = tid & 15;       // 0..15
    const int ty = tid >> 4;       // 0..15
    const int bm = blockIdx.y * 128;
    const int bn = blockIdx.x * 128;

    // gmem load mapping: thread loads one float4 from A and one from W per BK step
    const int lr = tid >> 1;            // 0..127 (row within tile)
    const int lc = (tid & 1) * 4;       // 0 or 4 (k offset within BK)
    const float* Ap = A + (size_t)(bm + lr) * K + lc;
    const float* Wp = W + (size_t)(bn + lr) * K + lc;

    float acc[8][8];
#pragma unroll
    for (int i = 0; i < 8; i++)
#pragma unroll
        for (int j = 0; j < 8; j++) acc[i][j] = 0.0f;

    float4 av = *(const float4*)Ap;
    float4 wv = *(const float4*)Wp;

    for (int k0 = 0; k0 < K; k0 += 8) {
        // stage current tile into smem (transposed)
        As[lc + 0][lr] = av.x; As[lc + 1][lr] = av.y;
        As[lc + 2][lr] = av.z; As[lc + 3][lr] = av.w;
        Ws[lc + 0][lr] = wv.x; Ws[lc + 1][lr] = wv.y;
        Ws[lc + 2][lr] = wv.z; Ws[lc + 3][lr] = wv.w;
        __syncthreads();

        // prefetch next tile (overlap gmem latency with compute)
        if (k0 + 8 < K) {
            av = *(const float4*)(Ap + k0 + 8);
            wv = *(const float4*)(Wp + k0 + 8);
        }

#pragma unroll
        for (int k = 0; k < 8; k++) {
            float a[8], b[8];
            *(float4*)(a)     = *(const float4*)&As[k][ty * 8];
            *(float4*)(a + 4) = *(const float4*)&As[k][ty * 8 + 4];
            *(float4*)(b)     = *(const float4*)&Ws[k][tx * 8];
            *(float4*)(b + 4) = *(const float4*)&Ws[k][tx * 8 + 4];
#pragma unroll
            for (int i = 0; i < 8; i++)
#pragma unroll
                for (int j = 0; j < 8; j++)
                    acc[i][j] = fmaf(a[i], b[j], acc[i][j]);
        }
        __syncthreads();
    }

    // epilogue
#pragma unroll
    for (int i = 0; i < 8; i++) {
        const int row = bm + ty * 8 + i;
#pragma unroll
        for (int j = 0; j < 8; j++) {
            const int col = bn + tx * 8 + j;
            const float v = acc[i][j] + bias[col];
            if (MODE == 0) {
                C[(size_t)row * N + col] = v;
            } else {
                const int bb = row >> 11;          // row / S_  (S_ = 2048)
                const int ss = row & (S_ - 1);
                const int h  = col >> 6;           // col / DH_
                const int dh = col & (DH_ - 1);
                C[(((size_t)(bb * H_ + h)) * S_ + ss) * DH_ + dh] = v;
            }
        }
    }
}

// ---------------------------------------------------------------------------
// Sigmoid attention, per (b,h): O = sigmoid(Q K^T / 8) V
// Q tile: 128 rows; KV tile: 128 rows; Dh = 64.
// 256 threads. Strided thread tiles (col = tx + 16*j) => conflict-free LDS
// for the B operands. Ks padded to 65 floats/row for k-indexed column reads.
// Dynamic smem: Qs[128*64] Ks[128*65] Vs[128*64] Ps[128*128] = 164352 B.
// ---------------------------------------------------------------------------
__global__ __launch_bounds__(256) void attn_kernel(
    const float* __restrict__ Qg, const float* __restrict__ Kg,
    const float* __restrict__ Vg, float* __restrict__ Og)
{
    extern __shared__ float sm[];
    float* Qs = sm;                    // [128][64]
    float* Ks = Qs + 128 * 64;         // [128][65]
    float* Vs = Ks + 128 * 65;         // [128][64]
    float* Ps = Vs + 128 * 64;         // [128][128]

    const int tid = threadIdx.x;
    const int tx = tid & 15;
    const int ty = tid >> 4;
    const int bh = blockIdx.y;             // 0..63  (b*H + h)
    const int q0 = blockIdx.x * 128;

    const float* Qp = Qg + (size_t)bh * S_ * DH_;
    const float* Kp = Kg + (size_t)bh * S_ * DH_;
    const float* Vp = Vg + (size_t)bh * S_ * DH_;

    // load Q tile [128,64] once (2048 float4s, 8 per thread)
#pragma unroll
    for (int it = 0; it < 8; it++) {
        const int f = tid + it * 256;
        const int r = f >> 4;
        const int c = (f & 15) << 2;
        *(float4*)&Qs[r * 64 + c] =
            *(const float4*)(Qp + (size_t)(q0 + r) * DH_ + c);
    }

    float o[8][4];
#pragma unroll
    for (int i = 0; i < 8; i++)
#pragma unroll
        for (int j = 0; j < 4; j++) o[i][j] = 0.0f;

    for (int j0 = 0; j0 < S_; j0 += 128) {
        __syncthreads();  // prev iter's Ps/Vs reads complete before overwrite

        // load K (padded 65) and V (stride 64) tiles
#pragma unroll
        for (int it = 0; it < 8; it++) {
            const int f = tid + it * 256;
            const int r = f >> 4;
            const int c = (f & 15) << 2;
            const float4 kv = *(const float4*)(Kp + (size_t)(j0 + r) * DH_ + c);
            float* kd = &Ks[r * 65 + c];
            kd[0] = kv.x; kd[1] = kv.y; kd[2] = kv.z; kd[3] = kv.w;
            *(float4*)&Vs[r * 64 + c] =
                *(const float4*)(Vp + (size_t)(j0 + r) * DH_ + c);
        }
        __syncthreads();

        // Stage 1: S[128q x 128kv] = Q * K^T ; each thread: rows ty+16i, cols tx+16j
        float s[8][8];
#pragma unroll
        for (int i = 0; i < 8; i++)
#pragma unroll
            for (int j = 0; j < 8; j++) s[i][j] = 0.0f;

#pragma unroll 8
        for (int k = 0; k < DH_; k++) {
            float a[8], b[8];
#pragma unroll
            for (int i = 0; i < 8; i++) a[i] = Qs[(ty + 16 * i) * 64 + k];
#pragma unroll
            for (int j = 0; j < 8; j++) b[j] = Ks[(tx + 16 * j) * 65 + k];
#pragma unroll
            for (int i = 0; i < 8; i++)
#pragma unroll
                for (int j = 0; j < 8; j++)
                    s[i][j] = fmaf(a[i], b[j], s[i][j]);
        }

        // sigmoid(s/8) -> Ps
#pragma unroll
        for (int i = 0; i < 8; i++)
#pragma unroll
            for (int j = 0; j < 8; j++) {
                const float x = s[i][j] * 0.125f;
                Ps[(ty + 16 * i) * 128 + (tx + 16 * j)] =
                    __fdividef(1.0f, 1.0f + __expf(-x));
            }
        __syncthreads();

        // Stage 2: O[128q x 64dh] += P * V ; each thread: rows ty+16i, cols tx+16j (j<4)
#pragma unroll 8
        for (int k = 0; k < 128; k++) {
            float p[8], vv[4];
#pragma unroll
            for (int i = 0; i < 8; i++) p[i] = Ps[(ty + 16 * i) * 128 + k];
#pragma unroll
            for (int j = 0; j < 4; j++) vv[j] = Vs[k * 64 + (tx + 16 * j)];
#pragma unroll
            for (int i = 0; i < 8; i++)
#pragma unroll
                for (int j = 0; j < 4; j++)
                    o[i][j] = fmaf(p[i], vv[j], o[i][j]);
        }
    }

    // write O to concat layout [B,S,D]: o_concat[b][s][h*64+dh]
    const int bb = bh >> 4;
    const int h  = bh & (H_ - 1);
#pragma unroll
    for (int i = 0; i < 8; i++) {
        const int srow = q0 + ty + 16 * i;
#pragma unroll
        for (int j = 0; j < 4; j++) {
            const int dh = tx + 16 * j;
            Og[((size_t)bb * S_ + srow) * D_ + h * DH_ + dh] = o[i][j];
        }
    }
}

// ---------------------------------------------------------------------------
// Launcher
// ---------------------------------------------------------------------------
extern "C" void kernel_launch(void* const* d_in, const int* in_sizes, int n_in,
                              void* d_out, int out_size)
{
    const float* q  = (const float*)d_in[0];
    const float* k  = (const float*)d_in[1];
    const float* v  = (const float*)d_in[2];
    const float* Wq = (const float*)d_in[3];
    const float* bq = (const float*)d_in[4];
    const float* Wk = (const float*)d_in[5];
    const float* bk = (const float*)d_in[6];
    const float* Wv = (const float*)d_in[7];
    const float* bv = (const float*)d_in[8];
    const float* Wo = (const float*)d_in[9];
    const float* bo = (const float*)d_in[10];
    float* out = (float*)d_out;

    float *gq, *gk, *gv, *go;
    cudaGetSymbolAddress((void**)&gq, g_q);
    cudaGetSymbolAddress((void**)&gk, g_k);
    cudaGetSymbolAddress((void**)&gv, g_v);
    cudaGetSymbolAddress((void**)&go, g_o);

    const dim3 gg(D_ / 128, M_ / 128);  // (8, 64)

    gemm_nt<1><<<gg, 256>>>(q, Wq, bq, gq, M_, D_, D_);
    gemm_nt<1><<<gg, 256>>>(k, Wk, bk, gk, M_, D_, D_);
    gemm_nt<1><<<gg, 256>>>(v, Wv, bv, gv, M_, D_, D_);

    const int attn_smem = (128 * 64 + 128 * 65 + 128 * 64 + 128 * 128) * (int)sizeof(float);
    cudaFuncSetAttribute(attn_kernel, cudaFuncAttributeMaxDynamicSharedMemorySize, attn_smem);
    attn_kernel<<<dim3(S_ / 128, B_ * H_), 256, attn_smem>>>(gq, gk, gv, go);

    gemm_nt<0><<<gg, 256>>>(go, Wo, bo, out, M_, D_, D_);
}